// round 14
// baseline (speedup 1.0000x reference)
#include <cuda_runtime.h>
#include <cuda_fp16.h>
#include <math.h>
#include <stdint.h>
#include <float.h>

#define D 256
#define KCODES 1024
#define N_MAX 32768
#define TAU 0.15f

#define BM 128
#define BN 128
#define NC_IT (KCODES / BN)   // 8

// Scratch (no cudaMalloc allowed)
__device__ __align__(128) float g_w2[KCODES];
__device__ int   g_idx[N_MAX];
__device__ int   g_counts[KCODES];
__device__ float g_partials[N_MAX];
__device__ int   g_flag[N_MAX];
__device__ int   g_nflag;
__device__ __align__(128) __half g_zh[(size_t)N_MAX * D];      // 16MB
__device__ __align__(128) __half g_wh[(size_t)KCODES * D];     // 512KB
__device__ __align__(128) float  g_wT[(size_t)D * KCODES];     // 1MB transposed

// ============================ PTX helpers (non-'a' arch only) ================
__device__ __forceinline__ uint32_t smem_u32(const void* p) {
    uint32_t a;
    asm("{ .reg .u64 t; cvta.to.shared.u64 t, %1; cvt.u32.u64 %0, t; }"
        : "=r"(a) : "l"(p));
    return a;
}
__device__ __forceinline__ void cp16(uint32_t dst, const void* src) {
    asm volatile("cp.async.cg.shared.global [%0], [%1], 16;" :: "r"(dst), "l"(src));
}
#define CP_COMMIT() asm volatile("cp.async.commit_group;" ::: "memory")
#define CP_WAIT0()  asm volatile("cp.async.wait_group 0;"  ::: "memory")
#define CP_WAIT7()  asm volatile("cp.async.wait_group 7;"  ::: "memory")

__device__ __forceinline__ void ldsm4(uint32_t* r, uint32_t addr) {
    asm volatile("ldmatrix.sync.aligned.m8n8.x4.shared.b16 {%0,%1,%2,%3}, [%4];"
        : "=r"(r[0]), "=r"(r[1]), "=r"(r[2]), "=r"(r[3]) : "r"(addr));
}
__device__ __forceinline__ void mma16816(float* c, const uint32_t* a,
                                         uint32_t b0, uint32_t b1) {
    asm volatile(
        "mma.sync.aligned.m16n8k16.row.col.f32.f16.f16.f32 "
        "{%0,%1,%2,%3}, {%4,%5,%6,%7}, {%8,%9}, {%0,%1,%2,%3};"
        : "+f"(c[0]), "+f"(c[1]), "+f"(c[2]), "+f"(c[3])
        : "r"(a[0]), "r"(a[1]), "r"(a[2]), "r"(a[3]), "r"(b0), "r"(b1));
}

// SMEM layout (GEMM)
#define OFF_A   0
#define OFF_B0  65536
#define OFF_B1  131072
#define OFF_RB1 196608      // float[256]
#define OFF_RI1 197632      // int[256]
#define OFF_RB2 198656      // float[256]
#define OFF_W2  199680      // float[1024]
#define SMEM_BYTES 203776

// SMEM layout (rescore, dynamic)
#define RS_Z    0           // float[4][256]  (4KB)
#define RS_BUF  4096        // 16-row ring: 16 x 256 threads x 16B = 64KB
#define RS_RV   69632       // float[4][256]  (4KB)
#define RS_RIX  73728       // int[4][256]    (4KB)
#define RS_BYTES 77824

// ============================ prep: zero + w fp16 + ||w||^2 + transpose ======
__global__ void prep_kernel(const float* __restrict__ w) {
    const int tid = threadIdx.x;
    const int bid = blockIdx.x;
    if (bid < 4) {
        g_counts[bid * 256 + tid] = 0;
        if (bid == 0 && tid == 0) g_nflag = 0;
    }
    const int code = (bid * 256 + tid) >> 5;
    const int lane = tid & 31;
    const float4* src = (const float4*)(w + (size_t)code * D);
    float4 v0 = src[lane * 2];
    float4 v1 = src[lane * 2 + 1];
    float s = v0.x * v0.x + v0.y * v0.y + v0.z * v0.z + v0.w * v0.w
            + v1.x * v1.x + v1.y * v1.y + v1.z * v1.z + v1.w * v1.w;
    __half2 h0 = __floats2half2_rn(v0.x, v0.y);
    __half2 h1 = __floats2half2_rn(v0.z, v0.w);
    __half2 h2 = __floats2half2_rn(v1.x, v1.y);
    __half2 h3 = __floats2half2_rn(v1.z, v1.w);
    uint4 u;
    u.x = *(uint32_t*)&h0; u.y = *(uint32_t*)&h1;
    u.z = *(uint32_t*)&h2; u.w = *(uint32_t*)&h3;
    *(uint4*)(g_wh + (size_t)code * D + lane * 8) = u;
    const int k0 = lane * 8;
    g_wT[(size_t)(k0 + 0) * KCODES + code] = v0.x;
    g_wT[(size_t)(k0 + 1) * KCODES + code] = v0.y;
    g_wT[(size_t)(k0 + 2) * KCODES + code] = v0.z;
    g_wT[(size_t)(k0 + 3) * KCODES + code] = v0.w;
    g_wT[(size_t)(k0 + 4) * KCODES + code] = v1.x;
    g_wT[(size_t)(k0 + 5) * KCODES + code] = v1.y;
    g_wT[(size_t)(k0 + 6) * KCODES + code] = v1.z;
    g_wT[(size_t)(k0 + 7) * KCODES + code] = v1.w;
#pragma unroll
    for (int o = 16; o; o >>= 1) s += __shfl_xor_sync(0xffffffffu, s, o);
    if (lane == 0) g_w2[code] = s;
}

// ============================ convert z -> fp16 ==============================
__global__ void convert_z_kernel(const float* __restrict__ z) {
    const int nz4 = N_MAX * D / 4;
    for (int i = blockIdx.x * blockDim.x + threadIdx.x; i < nz4;
         i += gridDim.x * blockDim.x) {
        float4 v = ((const float4*)z)[i];
        __half2 h0 = __floats2half2_rn(v.x, v.y);
        __half2 h1 = __floats2half2_rn(v.z, v.w);
        uint2 u;
        u.x = *(uint32_t*)&h0;
        u.y = *(uint32_t*)&h1;
        ((uint2*)g_zh)[i] = u;
    }
}

// ============================ GEMM + fused argmin (512 thr, round-9) =========
__global__ void __launch_bounds__(512, 1)
vq_gemm_kernel(float* __restrict__ out_idx_f) {
    extern __shared__ __align__(128) char smem[];
    const int tid = threadIdx.x;
    const int lane = tid & 31;
    const int wid = tid >> 5;
    const int wm = wid & 7;          // 8 row bands of 16
    const int wn = wid >> 3;         // 2 col bands of 64
    const int row_w = wm * 16;
    const int col_w = wn * 64;
    const int row0 = blockIdx.x * BM;

    const uint32_t sb = smem_u32(smem);
    const uint32_t sA = sb + OFF_A;
    float* redB1 = (float*)(smem + OFF_RB1);
    int*   redI1 = (int*)(smem + OFF_RI1);
    float* redB2 = (float*)(smem + OFF_RB2);
    float* sw2   = (float*)(smem + OFF_W2);

    {
        const __half* zA = g_zh + (size_t)row0 * D;
#pragma unroll
        for (int i = 0; i < 8; i++) {
            int idx = tid + i * 512;
            int r = idx >> 5, c = idx & 31;
            cp16(sA + r * 512 + (((c & 24) | ((c ^ (r & 7)) & 7)) << 4),
                 zA + (size_t)r * D + c * 8);
        }
    }
#pragma unroll
    for (int i = 0; i < 8; i++) {
        int idx = tid + i * 512;
        int r = idx >> 5, c = idx & 31;
        cp16(sb + OFF_B0 + r * 512 + (((c & 24) | ((c ^ (r & 7)) & 7)) << 4),
             g_wh + (size_t)r * D + c * 8);
    }
    CP_COMMIT();

#pragma unroll
    for (int i = 0; i < 2; i++) sw2[tid + i * 512] = g_w2[tid + i * 512];

    float rb1 = FLT_MAX, rb2 = FLT_MAX;
    int ri1 = 0;
    const int within = lane & 7;
    const int sel = lane >> 3;

    for (int nc = 0; nc < NC_IT; nc++) {
        CP_WAIT0();
        __syncthreads();
        if (nc < NC_IT - 1) {
            const __half* src = g_wh + (size_t)(nc + 1) * BN * D;
            uint32_t dstb = sb + ((nc + 1) & 1 ? OFF_B1 : OFF_B0);
#pragma unroll
            for (int i = 0; i < 8; i++) {
                int idx = tid + i * 512;
                int r = idx >> 5, c = idx & 31;
                cp16(dstb + r * 512 + (((c & 24) | ((c ^ (r & 7)) & 7)) << 4),
                     src + (size_t)r * D + c * 8);
            }
            CP_COMMIT();
        }
        const uint32_t sBc = sb + ((nc & 1) ? OFF_B1 : OFF_B0);

        float cacc[8][4];
#pragma unroll
        for (int ni = 0; ni < 8; ni++)
#pragma unroll
            for (int e = 0; e < 4; e++) cacc[ni][e] = 0.f;

#pragma unroll
        for (int ks = 0; ks < 16; ks++) {
            uint32_t a[4];
            {
                int ra = row_w + ((sel & 1) << 3) + within;
                int ca = ks * 2 + (sel >> 1);
                ldsm4(a, sA + ra * 512 + (((ca & 24) | ((ca ^ (ra & 7)) & 7)) << 4));
            }
            uint32_t b[4][4];
#pragma unroll
            for (int p = 0; p < 4; p++) {
                int rb = col_w + p * 16 + ((sel >> 1) << 3) + within;
                int cb = ks * 2 + (sel & 1);
                ldsm4(b[p], sBc + rb * 512 + (((cb & 24) | ((cb ^ (rb & 7)) & 7)) << 4));
            }
#pragma unroll
            for (int ni = 0; ni < 8; ni++) {
                const int p = ni >> 1;
                if (ni & 1) mma16816(cacc[ni], a, b[p][2], b[p][3]);
                else        mma16816(cacc[ni], a, b[p][0], b[p][1]);
            }
        }

#pragma unroll
        for (int h = 0; h < 2; h++) {
            float v1 = FLT_MAX, v2 = FLT_MAX;
            int j1 = 0;
#pragma unroll
            for (int ni = 0; ni < 8; ni++)
#pragma unroll
                for (int e = 0; e < 2; e++) {
                    int gcol = nc * BN + col_w + ni * 8 + ((lane & 3) << 1) + e;
                    float sc = sw2[gcol] - 2.f * cacc[ni][h * 2 + e];
                    if (sc < v1) { v2 = v1; v1 = sc; j1 = gcol; }
                    else if (sc < v2) v2 = sc;
                }
#pragma unroll
            for (int off = 1; off <= 2; off <<= 1) {
                float o1 = __shfl_xor_sync(0xffffffffu, v1, off);
                int oj   = __shfl_xor_sync(0xffffffffu, j1, off);
                float o2 = __shfl_xor_sync(0xffffffffu, v2, off);
                if (o1 < v1 || (o1 == v1 && oj < j1)) {
                    v2 = fminf(v1, o2); v1 = o1; j1 = oj;
                } else {
                    v2 = fminf(v2, o1);
                }
            }
            if ((lane & 3) == 0) {
                int r = row_w + (lane >> 2) + h * 8;
                redB1[wn * 128 + r] = v1;
                redI1[wn * 128 + r] = j1;
                redB2[wn * 128 + r] = v2;
            }
        }
        __syncthreads();
        if (tid < 128) {
            float a1 = redB1[tid], a2 = redB2[tid];
            int aj = redI1[tid];
            float c1 = redB1[128 + tid], c2 = redB2[128 + tid];
            int cj = redI1[128 + tid];
            if (c1 < a1 || (c1 == a1 && cj < aj)) { a2 = fminf(a1, c2); a1 = c1; aj = cj; }
            else a2 = fminf(a2, c1);
            if (a1 < rb1 || (a1 == rb1 && aj < ri1)) { rb2 = fminf(rb1, a2); rb1 = a1; ri1 = aj; }
            else rb2 = fminf(rb2, a1);
        }
        __syncthreads();
    }

    if (tid < 128) {
        int row = row0 + tid;
        g_idx[row] = ri1;
        out_idx_f[row] = (float)ri1;
        atomicAdd(&g_counts[ri1], 1);
        if (rb2 - rb1 < TAU) {
            int p = atomicAdd(&g_nflag, 1);
            g_flag[p] = row;
        }
    }
}

// ============================ Exact rescore (barrier-free cp.async ring) =====
// 4 tokens/block; thread owns 4 consecutive codes (one float4 per wT row).
// Each thread streams ITS OWN 16B of every wT row through a private slot of a
// 16-row ring via cp.async (depth-8 window, wait_group 7). Same-thread
// visibility after wait_group => no __syncthreads in the k-loop. Overwrite of
// slot (k+8)&15 happens 8 iterations after its LDS -- no race. Tail commits
// empty groups to keep the group count constant so wait_group 7 always pins
// the oldest outstanding row.
__global__ void __launch_bounds__(256)
rescore_kernel(const float* __restrict__ z, float* __restrict__ out_idx_f) {
    extern __shared__ __align__(128) char rsm[];
    float (*zs)[D] = (float(*)[D])(rsm + RS_Z);
    float (*rv)[256] = (float(*)[256])(rsm + RS_RV);
    int   (*rix)[256] = (int(*)[256])(rsm + RS_RIX);
    const uint32_t rbase = smem_u32(rsm) + RS_BUF;
    const int tid = threadIdx.x;
    const int nf = g_nflag;
    const float* wsrc = g_wT + tid * 4;   // this thread's 4 codes, row stride 1024

    for (int base = blockIdx.x * 4; base < nf; base += gridDim.x * 4) {
        CP_WAIT0();
        __syncthreads();
        for (int j = tid; j < 4 * D; j += 256) {
            int t = j >> 8;
            int tok = (base + t < nf) ? g_flag[base + t] : g_flag[base];
            zs[t][j & 255] = z[(size_t)tok * D + (j & 255)];
        }
        __syncthreads();

        // prefill rows 0..7 (8 groups in flight)
#pragma unroll
        for (int r = 0; r < 8; r++) {
            cp16(rbase + (uint32_t)((r * 256 + tid) * 16), wsrc + (size_t)r * KCODES);
            CP_COMMIT();
        }

        float acc[4][4];
#pragma unroll
        for (int t = 0; t < 4; t++)
#pragma unroll
            for (int j = 0; j < 4; j++) acc[t][j] = 0.f;

        for (int k = 0; k < D; k++) {
            CP_WAIT7();                   // row k complete (oldest of 8)
            float4 wv = *(const float4*)(rsm + RS_BUF + ((k & 15) * 256 + tid) * 16);
            float z0 = zs[0][k], z1 = zs[1][k], z2 = zs[2][k], z3 = zs[3][k];
            acc[0][0] += wv.x * z0; acc[0][1] += wv.y * z0;
            acc[0][2] += wv.z * z0; acc[0][3] += wv.w * z0;
            acc[1][0] += wv.x * z1; acc[1][1] += wv.y * z1;
            acc[1][2] += wv.z * z1; acc[1][3] += wv.w * z1;
            acc[2][0] += wv.x * z2; acc[2][1] += wv.y * z2;
            acc[2][2] += wv.z * z2; acc[2][3] += wv.w * z2;
            acc[3][0] += wv.x * z3; acc[3][1] += wv.y * z3;
            acc[3][2] += wv.z * z3; acc[3][3] += wv.w * z3;
            if (k + 8 < D)
                cp16(rbase + (uint32_t)((((k + 8) & 15) * 256 + tid) * 16),
                     wsrc + (size_t)(k + 8) * KCODES);
            CP_COMMIT();                  // real or empty: keeps count at 8
        }

        float4 w2v = ((const float4*)g_w2)[tid];
#pragma unroll
        for (int t = 0; t < 4; t++) {
            float s0 = w2v.x - 2.f * acc[t][0];
            float s1 = w2v.y - 2.f * acc[t][1];
            float s2 = w2v.z - 2.f * acc[t][2];
            float s3 = w2v.w - 2.f * acc[t][3];
            float bv = s0; int bj = 0;
            if (s1 < bv) { bv = s1; bj = 1; }
            if (s2 < bv) { bv = s2; bj = 2; }
            if (s3 < bv) { bv = s3; bj = 3; }
            rv[t][tid] = bv;
            rix[t][tid] = tid * 4 + bj;
        }
        __syncthreads();
        for (int off = 128; off; off >>= 1) {
            if (tid < off) {
#pragma unroll
                for (int t = 0; t < 4; t++) {
                    float ov = rv[t][tid + off]; int oi = rix[t][tid + off];
                    if (ov < rv[t][tid] || (ov == rv[t][tid] && oi < rix[t][tid])) {
                        rv[t][tid] = ov; rix[t][tid] = oi;
                    }
                }
            }
            __syncthreads();
        }
        if (tid < 4 && base + tid < nf) {
            int tok = g_flag[base + tid];
            int ni = rix[tid][0], old = g_idx[tok];
            if (ni != old) {
                atomicSub(&g_counts[old], 1);
                atomicAdd(&g_counts[ni], 1);
                g_idx[tok] = ni;
                out_idx_f[tok] = (float)ni;
            }
        }
    }
}

// ============================ Gather + loss (after rescore) ==================
__global__ void gather_kernel(const float* __restrict__ z, const float* __restrict__ w,
                              float* __restrict__ out_zq) {
    __shared__ float sred[8];
    const int tid = threadIdx.x;
    const int sub = tid >> 6;
    const int t = tid & 63;
    const int token = blockIdx.x * 4 + sub;
    const int idx = g_idx[token];
    float4 q = *(const float4*)&w[(size_t)idx * D + t * 4];
    float4 v = *(const float4*)&z[(size_t)token * D + t * 4];
    float* o = &out_zq[(size_t)token * D + t * 4];
    o[0] = q.x; o[1] = q.y; o[2] = q.z; o[3] = q.w;   // scalar: out_zq 4B-aligned
    float dx = q.x - v.x, dy = q.y - v.y, dz = q.z - v.z, dw = q.w - v.w;
    float s = dx * dx + dy * dy + dz * dz + dw * dw;
#pragma unroll
    for (int o2 = 16; o2; o2 >>= 1) s += __shfl_xor_sync(0xffffffffu, s, o2);
    if ((tid & 31) == 0) sred[tid >> 5] = s;
    __syncthreads();
    if (tid < 4) g_partials[blockIdx.x * 4 + tid] = sred[2 * tid] + sred[2 * tid + 1];
}

// ============================ Finalize =======================================
__global__ void finalize_kernel(float* __restrict__ out_loss,
                                float* __restrict__ out_perp, int N) {
    __shared__ float red[1024];
    int t = threadIdx.x;
    float s = 0.f;
    for (int i = t; i < N; i += 1024) s += g_partials[i];
    red[t] = s;
    __syncthreads();
#pragma unroll
    for (int o = 512; o; o >>= 1) {
        if (t < o) red[t] += red[t + o];
        __syncthreads();
    }
    if (t == 0) out_loss[0] = 0.25f * red[0] / (float)(N * D);
    __syncthreads();
    float e = (float)g_counts[t] / (float)N;
    red[t] = e * logf(e + 1e-10f);
    __syncthreads();
#pragma unroll
    for (int o = 512; o; o >>= 1) {
        if (t < o) red[t] += red[t + o];
        __syncthreads();
    }
    if (t == 0) out_perp[0] = expf(-red[0]);
}

// ============================================================================
extern "C" void kernel_launch(void* const* d_in, const int* in_sizes, int n_in,
                              void* d_out, int out_size) {
    const float* z = (const float*)d_in[0];
    const float* w = (const float*)d_in[1];
    float* out = (float*)d_out;

    const int N = in_sizes[0] / D;  // 32768

    float* out_loss = out;
    float* out_zq   = out + 1;
    float* out_idx  = out + 1 + (size_t)N * D;
    float* out_perp = out + 1 + (size_t)N * D + N;

    cudaFuncSetAttribute(vq_gemm_kernel,
                         cudaFuncAttributeMaxDynamicSharedMemorySize, SMEM_BYTES);
    cudaFuncSetAttribute(rescore_kernel,
                         cudaFuncAttributeMaxDynamicSharedMemorySize, RS_BYTES);

    convert_z_kernel<<<2048, 256>>>(z);
    prep_kernel<<<128, 256>>>(w);
    vq_gemm_kernel<<<N / BM, 512, SMEM_BYTES>>>(out_idx);
    rescore_kernel<<<256, 256, RS_BYTES>>>(z, out_idx);
    gather_kernel<<<N / 4, 256>>>(z, w, out_zq);
    finalize_kernel<<<1, 1024>>>(out_loss, out_perp, N);
}

// round 15
// speedup vs baseline: 1.2107x; 1.2107x over previous
#include <cuda_runtime.h>
#include <cuda_fp16.h>
#include <math.h>
#include <stdint.h>
#include <float.h>

#define D 256
#define KCODES 1024
#define N_MAX 32768
#define TAU 0.15f

#define BM 128
#define BN 128
#define NC_IT (KCODES / BN)   // 8

// Scratch (no cudaMalloc allowed)
__device__ __align__(128) float g_w2[KCODES];
__device__ int   g_idx[N_MAX];
__device__ int   g_counts[KCODES];
__device__ float g_partials[N_MAX];
__device__ int   g_flag[N_MAX];
__device__ int   g_nflag;
__device__ __align__(128) __half g_zh[(size_t)N_MAX * D];      // 16MB
__device__ __align__(128) __half g_wh[(size_t)KCODES * D];     // 512KB
__device__ __align__(128) float  g_wT[(size_t)D * KCODES];     // 1MB transposed

// ============================ PTX helpers (non-'a' arch only) ================
__device__ __forceinline__ uint32_t smem_u32(const void* p) {
    uint32_t a;
    asm("{ .reg .u64 t; cvta.to.shared.u64 t, %1; cvt.u32.u64 %0, t; }"
        : "=r"(a) : "l"(p));
    return a;
}
__device__ __forceinline__ void cp16(uint32_t dst, const void* src) {
    asm volatile("cp.async.cg.shared.global [%0], [%1], 16;" :: "r"(dst), "l"(src));
}
#define CP_COMMIT() asm volatile("cp.async.commit_group;" ::: "memory")
#define CP_WAIT0()  asm volatile("cp.async.wait_group 0;"  ::: "memory")
#define CP_WAIT1()  asm volatile("cp.async.wait_group 1;"  ::: "memory")

__device__ __forceinline__ void ldsm4(uint32_t* r, uint32_t addr) {
    asm volatile("ldmatrix.sync.aligned.m8n8.x4.shared.b16 {%0,%1,%2,%3}, [%4];"
        : "=r"(r[0]), "=r"(r[1]), "=r"(r[2]), "=r"(r[3]) : "r"(addr));
}
__device__ __forceinline__ void mma16816(float* c, const uint32_t* a,
                                         uint32_t b0, uint32_t b1) {
    asm volatile(
        "mma.sync.aligned.m16n8k16.row.col.f32.f16.f16.f32 "
        "{%0,%1,%2,%3}, {%4,%5,%6,%7}, {%8,%9}, {%0,%1,%2,%3};"
        : "+f"(c[0]), "+f"(c[1]), "+f"(c[2]), "+f"(c[3])
        : "r"(a[0]), "r"(a[1]), "r"(a[2]), "r"(a[3]), "r"(b0), "r"(b1));
}

// SMEM layout (GEMM)
#define OFF_A   0
#define OFF_B0  65536
#define OFF_B1  131072
#define OFF_RB1 196608      // float[256]
#define OFF_RI1 197632      // int[256]
#define OFF_RB2 198656      // float[256]
#define OFF_W2  199680      // float[1024]
#define SMEM_BYTES 203776

// SMEM layout (rescore, dynamic): 1 token/block, 1024 threads
#define RS_Z    0           // float[256]   (1KB)
#define RS_BUF  1024        // 2 x 16 rows x 1024 floats = 128KB
#define RS_RV   132096      // float[1024]  (4KB)
#define RS_RIX  136192      // int[1024]    (4KB)
#define RS_BYTES 140288

// ============================ prep: zero + w fp16 + ||w||^2 + transpose ======
__global__ void prep_kernel(const float* __restrict__ w) {
    const int tid = threadIdx.x;
    const int bid = blockIdx.x;
    if (bid < 4) {
        g_counts[bid * 256 + tid] = 0;
        if (bid == 0 && tid == 0) g_nflag = 0;
    }
    const int code = (bid * 256 + tid) >> 5;
    const int lane = tid & 31;
    const float4* src = (const float4*)(w + (size_t)code * D);
    float4 v0 = src[lane * 2];
    float4 v1 = src[lane * 2 + 1];
    float s = v0.x * v0.x + v0.y * v0.y + v0.z * v0.z + v0.w * v0.w
            + v1.x * v1.x + v1.y * v1.y + v1.z * v1.z + v1.w * v1.w;
    __half2 h0 = __floats2half2_rn(v0.x, v0.y);
    __half2 h1 = __floats2half2_rn(v0.z, v0.w);
    __half2 h2 = __floats2half2_rn(v1.x, v1.y);
    __half2 h3 = __floats2half2_rn(v1.z, v1.w);
    uint4 u;
    u.x = *(uint32_t*)&h0; u.y = *(uint32_t*)&h1;
    u.z = *(uint32_t*)&h2; u.w = *(uint32_t*)&h3;
    *(uint4*)(g_wh + (size_t)code * D + lane * 8) = u;
    const int k0 = lane * 8;
    g_wT[(size_t)(k0 + 0) * KCODES + code] = v0.x;
    g_wT[(size_t)(k0 + 1) * KCODES + code] = v0.y;
    g_wT[(size_t)(k0 + 2) * KCODES + code] = v0.z;
    g_wT[(size_t)(k0 + 3) * KCODES + code] = v0.w;
    g_wT[(size_t)(k0 + 4) * KCODES + code] = v1.x;
    g_wT[(size_t)(k0 + 5) * KCODES + code] = v1.y;
    g_wT[(size_t)(k0 + 6) * KCODES + code] = v1.z;
    g_wT[(size_t)(k0 + 7) * KCODES + code] = v1.w;
#pragma unroll
    for (int o = 16; o; o >>= 1) s += __shfl_xor_sync(0xffffffffu, s, o);
    if (lane == 0) g_w2[code] = s;
}

// ============================ convert z -> fp16 ==============================
__global__ void convert_z_kernel(const float* __restrict__ z) {
    const int nz4 = N_MAX * D / 4;
    for (int i = blockIdx.x * blockDim.x + threadIdx.x; i < nz4;
         i += gridDim.x * blockDim.x) {
        float4 v = ((const float4*)z)[i];
        __half2 h0 = __floats2half2_rn(v.x, v.y);
        __half2 h1 = __floats2half2_rn(v.z, v.w);
        uint2 u;
        u.x = *(uint32_t*)&h0;
        u.y = *(uint32_t*)&h1;
        ((uint2*)g_zh)[i] = u;
    }
}

// ============================ GEMM + fused argmin (512 thr, round-9) =========
__global__ void __launch_bounds__(512, 1)
vq_gemm_kernel(float* __restrict__ out_idx_f) {
    extern __shared__ __align__(128) char smem[];
    const int tid = threadIdx.x;
    const int lane = tid & 31;
    const int wid = tid >> 5;
    const int wm = wid & 7;          // 8 row bands of 16
    const int wn = wid >> 3;         // 2 col bands of 64
    const int row_w = wm * 16;
    const int col_w = wn * 64;
    const int row0 = blockIdx.x * BM;

    const uint32_t sb = smem_u32(smem);
    const uint32_t sA = sb + OFF_A;
    float* redB1 = (float*)(smem + OFF_RB1);
    int*   redI1 = (int*)(smem + OFF_RI1);
    float* redB2 = (float*)(smem + OFF_RB2);
    float* sw2   = (float*)(smem + OFF_W2);

    {
        const __half* zA = g_zh + (size_t)row0 * D;
#pragma unroll
        for (int i = 0; i < 8; i++) {
            int idx = tid + i * 512;
            int r = idx >> 5, c = idx & 31;
            cp16(sA + r * 512 + (((c & 24) | ((c ^ (r & 7)) & 7)) << 4),
                 zA + (size_t)r * D + c * 8);
        }
    }
#pragma unroll
    for (int i = 0; i < 8; i++) {
        int idx = tid + i * 512;
        int r = idx >> 5, c = idx & 31;
        cp16(sb + OFF_B0 + r * 512 + (((c & 24) | ((c ^ (r & 7)) & 7)) << 4),
             g_wh + (size_t)r * D + c * 8);
    }
    CP_COMMIT();

#pragma unroll
    for (int i = 0; i < 2; i++) sw2[tid + i * 512] = g_w2[tid + i * 512];

    float rb1 = FLT_MAX, rb2 = FLT_MAX;
    int ri1 = 0;
    const int within = lane & 7;
    const int sel = lane >> 3;

    for (int nc = 0; nc < NC_IT; nc++) {
        CP_WAIT0();
        __syncthreads();
        if (nc < NC_IT - 1) {
            const __half* src = g_wh + (size_t)(nc + 1) * BN * D;
            uint32_t dstb = sb + ((nc + 1) & 1 ? OFF_B1 : OFF_B0);
#pragma unroll
            for (int i = 0; i < 8; i++) {
                int idx = tid + i * 512;
                int r = idx >> 5, c = idx & 31;
                cp16(dstb + r * 512 + (((c & 24) | ((c ^ (r & 7)) & 7)) << 4),
                     src + (size_t)r * D + c * 8);
            }
            CP_COMMIT();
        }
        const uint32_t sBc = sb + ((nc & 1) ? OFF_B1 : OFF_B0);

        float cacc[8][4];
#pragma unroll
        for (int ni = 0; ni < 8; ni++)
#pragma unroll
            for (int e = 0; e < 4; e++) cacc[ni][e] = 0.f;

#pragma unroll
        for (int ks = 0; ks < 16; ks++) {
            uint32_t a[4];
            {
                int ra = row_w + ((sel & 1) << 3) + within;
                int ca = ks * 2 + (sel >> 1);
                ldsm4(a, sA + ra * 512 + (((ca & 24) | ((ca ^ (ra & 7)) & 7)) << 4));
            }
            uint32_t b[4][4];
#pragma unroll
            for (int p = 0; p < 4; p++) {
                int rb = col_w + p * 16 + ((sel >> 1) << 3) + within;
                int cb = ks * 2 + (sel & 1);
                ldsm4(b[p], sBc + rb * 512 + (((cb & 24) | ((cb ^ (rb & 7)) & 7)) << 4));
            }
#pragma unroll
            for (int ni = 0; ni < 8; ni++) {
                const int p = ni >> 1;
                if (ni & 1) mma16816(cacc[ni], a, b[p][2], b[p][3]);
                else        mma16816(cacc[ni], a, b[p][0], b[p][1]);
            }
        }

#pragma unroll
        for (int h = 0; h < 2; h++) {
            float v1 = FLT_MAX, v2 = FLT_MAX;
            int j1 = 0;
#pragma unroll
            for (int ni = 0; ni < 8; ni++)
#pragma unroll
                for (int e = 0; e < 2; e++) {
                    int gcol = nc * BN + col_w + ni * 8 + ((lane & 3) << 1) + e;
                    float sc = sw2[gcol] - 2.f * cacc[ni][h * 2 + e];
                    if (sc < v1) { v2 = v1; v1 = sc; j1 = gcol; }
                    else if (sc < v2) v2 = sc;
                }
#pragma unroll
            for (int off = 1; off <= 2; off <<= 1) {
                float o1 = __shfl_xor_sync(0xffffffffu, v1, off);
                int oj   = __shfl_xor_sync(0xffffffffu, j1, off);
                float o2 = __shfl_xor_sync(0xffffffffu, v2, off);
                if (o1 < v1 || (o1 == v1 && oj < j1)) {
                    v2 = fminf(v1, o2); v1 = o1; j1 = oj;
                } else {
                    v2 = fminf(v2, o1);
                }
            }
            if ((lane & 3) == 0) {
                int r = row_w + (lane >> 2) + h * 8;
                redB1[wn * 128 + r] = v1;
                redI1[wn * 128 + r] = j1;
                redB2[wn * 128 + r] = v2;
            }
        }
        __syncthreads();
        if (tid < 128) {
            float a1 = redB1[tid], a2 = redB2[tid];
            int aj = redI1[tid];
            float c1 = redB1[128 + tid], c2 = redB2[128 + tid];
            int cj = redI1[128 + tid];
            if (c1 < a1 || (c1 == a1 && cj < aj)) { a2 = fminf(a1, c2); a1 = c1; aj = cj; }
            else a2 = fminf(a2, c1);
            if (a1 < rb1 || (a1 == rb1 && aj < ri1)) { rb2 = fminf(rb1, a2); rb1 = a1; ri1 = aj; }
            else rb2 = fminf(rb2, a1);
        }
        __syncthreads();
    }

    if (tid < 128) {
        int row = row0 + tid;
        g_idx[row] = ri1;
        out_idx_f[row] = (float)ri1;
        atomicAdd(&g_counts[ri1], 1);
        if (rb2 - rb1 < TAU) {
            int p = atomicAdd(&g_nflag, 1);
            g_flag[p] = row;
        }
    }
}

// ============================ Exact rescore (1 token/block, 1024 thr) ========
// Thread owns ONE code: 256 FMA total on the critical path (16x less than
// the 4-token variant). wT streamed via 16 double-buffered cp.async stages
// of 16 k-rows (64KB); stage time is L2-fetch-bound, compute is trivial.
__global__ void __launch_bounds__(1024)
rescore_kernel(const float* __restrict__ z, float* __restrict__ out_idx_f) {
    extern __shared__ __align__(128) char rsm[];
    float* zs = (float*)(rsm + RS_Z);
    float* rv = (float*)(rsm + RS_RV);
    int*   rix = (int*)(rsm + RS_RIX);
    const uint32_t sbuf = smem_u32(rsm) + RS_BUF;
    const int tid = threadIdx.x;
    const int nf = g_nflag;

    for (int f = blockIdx.x; f < nf; f += gridDim.x) {
        const int tok = g_flag[f];
        CP_WAIT0();
        __syncthreads();   // previous iteration's buffers fully consumed
        if (tid < D) zs[tid] = z[(size_t)tok * D + tid];

        // prefetch stage 0 (k rows 0..15): 4096 chunks, 4 per thread
#pragma unroll
        for (int j = 0; j < 4; j++) {
            int i = tid + j * 1024;
            int row = i >> 8, col = i & 255;
            cp16(sbuf + row * 4096 + col * 16, g_wT + (size_t)row * KCODES + col * 4);
        }
        CP_COMMIT();

        float acc = 0.f;
        for (int s = 0; s < 16; s++) {
            if (s + 1 < 16) {
                const float* src = g_wT + (size_t)(s + 1) * 16 * KCODES;
                uint32_t dst = sbuf + ((s + 1) & 1) * 65536;
#pragma unroll
                for (int j = 0; j < 4; j++) {
                    int i = tid + j * 1024;
                    int row = i >> 8, col = i & 255;
                    cp16(dst + row * 4096 + col * 16, src + (size_t)row * KCODES + col * 4);
                }
                CP_COMMIT();
                CP_WAIT1();
            } else {
                CP_WAIT0();
            }
            __syncthreads();

            const float* cur = (const float*)(rsm + RS_BUF + (s & 1) * 65536);
#pragma unroll
            for (int u = 0; u < 16; u++)
                acc += cur[u * 1024 + tid] * zs[s * 16 + u];
            __syncthreads();
        }

        rv[tid] = g_w2[tid] - 2.f * acc;
        rix[tid] = tid;
        __syncthreads();
        for (int off = 512; off; off >>= 1) {
            if (tid < off) {
                float ov = rv[tid + off]; int oi = rix[tid + off];
                if (ov < rv[tid] || (ov == rv[tid] && oi < rix[tid])) {
                    rv[tid] = ov; rix[tid] = oi;
                }
            }
            __syncthreads();
        }
        if (tid == 0) {
            int ni = rix[0], old = g_idx[tok];
            if (ni != old) {
                atomicSub(&g_counts[old], 1);
                atomicAdd(&g_counts[ni], 1);
                g_idx[tok] = ni;
                out_idx_f[tok] = (float)ni;
            }
        }
    }
}

// ============================ Gather + loss (after rescore) ==================
__global__ void gather_kernel(const float* __restrict__ z, const float* __restrict__ w,
                              float* __restrict__ out_zq) {
    __shared__ float sred[8];
    const int tid = threadIdx.x;
    const int sub = tid >> 6;
    const int t = tid & 63;
    const int token = blockIdx.x * 4 + sub;
    const int idx = g_idx[token];
    float4 q = *(const float4*)&w[(size_t)idx * D + t * 4];
    float4 v = *(const float4*)&z[(size_t)token * D + t * 4];
    float* o = &out_zq[(size_t)token * D + t * 4];
    o[0] = q.x; o[1] = q.y; o[2] = q.z; o[3] = q.w;   // scalar: out_zq 4B-aligned
    float dx = q.x - v.x, dy = q.y - v.y, dz = q.z - v.z, dw = q.w - v.w;
    float s = dx * dx + dy * dy + dz * dz + dw * dw;
#pragma unroll
    for (int o2 = 16; o2; o2 >>= 1) s += __shfl_xor_sync(0xffffffffu, s, o2);
    if ((tid & 31) == 0) sred[tid >> 5] = s;
    __syncthreads();
    if (tid < 4) g_partials[blockIdx.x * 4 + tid] = sred[2 * tid] + sred[2 * tid + 1];
}

// ============================ Finalize =======================================
__global__ void finalize_kernel(float* __restrict__ out_loss,
                                float* __restrict__ out_perp, int N) {
    __shared__ float red[1024];
    int t = threadIdx.x;
    float s = 0.f;
    for (int i = t; i < N; i += 1024) s += g_partials[i];
    red[t] = s;
    __syncthreads();
#pragma unroll
    for (int o = 512; o; o >>= 1) {
        if (t < o) red[t] += red[t + o];
        __syncthreads();
    }
    if (t == 0) out_loss[0] = 0.25f * red[0] / (float)(N * D);
    __syncthreads();
    float e = (float)g_counts[t] / (float)N;
    red[t] = e * logf(e + 1e-10f);
    __syncthreads();
#pragma unroll
    for (int o = 512; o; o >>= 1) {
        if (t < o) red[t] += red[t + o];
        __syncthreads();
    }
    if (t == 0) out_perp[0] = expf(-red[0]);
}

// ============================================================================
extern "C" void kernel_launch(void* const* d_in, const int* in_sizes, int n_in,
                              void* d_out, int out_size) {
    const float* z = (const float*)d_in[0];
    const float* w = (const float*)d_in[1];
    float* out = (float*)d_out;

    const int N = in_sizes[0] / D;  // 32768

    float* out_loss = out;
    float* out_zq   = out + 1;
    float* out_idx  = out + 1 + (size_t)N * D;
    float* out_perp = out + 1 + (size_t)N * D + N;

    cudaFuncSetAttribute(vq_gemm_kernel,
                         cudaFuncAttributeMaxDynamicSharedMemorySize, SMEM_BYTES);
    cudaFuncSetAttribute(rescore_kernel,
                         cudaFuncAttributeMaxDynamicSharedMemorySize, RS_BYTES);

    convert_z_kernel<<<2048, 256>>>(z);
    prep_kernel<<<128, 256>>>(w);
    vq_gemm_kernel<<<N / BM, 512, SMEM_BYTES>>>(out_idx);
    rescore_kernel<<<128, 1024, RS_BYTES>>>(z, out_idx);
    gather_kernel<<<N / 4, 256>>>(z, w, out_zq);
    finalize_kernel<<<1, 1024>>>(out_loss, out_perp, N);
}

// round 16
// speedup vs baseline: 1.5793x; 1.3045x over previous
#include <cuda_runtime.h>
#include <cuda_fp16.h>
#include <math.h>
#include <stdint.h>
#include <float.h>

#define D 256
#define KCODES 1024
#define N_MAX 32768
#define TAU 0.15f

#define BM 128
#define BN 128
#define NC_IT (KCODES / BN)   // 8

// Scratch (no cudaMalloc allowed)
__device__ __align__(128) float g_w2[KCODES];
__device__ int   g_idx[N_MAX];
__device__ int   g_counts[KCODES];
__device__ float g_partials[N_MAX];
__device__ int   g_flag[N_MAX];
__device__ int   g_nflag;
__device__ __align__(128) __half g_zh[(size_t)N_MAX * D];      // 16MB
__device__ __align__(128) __half g_wh[(size_t)KCODES * D];     // 512KB
__device__ __align__(128) float  g_wT[(size_t)D * KCODES];     // 1MB transposed

// ============================ PTX helpers (non-'a' arch only) ================
__device__ __forceinline__ uint32_t smem_u32(const void* p) {
    uint32_t a;
    asm("{ .reg .u64 t; cvta.to.shared.u64 t, %1; cvt.u32.u64 %0, t; }"
        : "=r"(a) : "l"(p));
    return a;
}
__device__ __forceinline__ void cp16(uint32_t dst, const void* src) {
    asm volatile("cp.async.cg.shared.global [%0], [%1], 16;" :: "r"(dst), "l"(src));
}
#define CP_COMMIT() asm volatile("cp.async.commit_group;" ::: "memory")
#define CP_WAIT0()  asm volatile("cp.async.wait_group 0;"  ::: "memory")
#define CP_WAIT1()  asm volatile("cp.async.wait_group 1;"  ::: "memory")

__device__ __forceinline__ void ldsm4(uint32_t* r, uint32_t addr) {
    asm volatile("ldmatrix.sync.aligned.m8n8.x4.shared.b16 {%0,%1,%2,%3}, [%4];"
        : "=r"(r[0]), "=r"(r[1]), "=r"(r[2]), "=r"(r[3]) : "r"(addr));
}
__device__ __forceinline__ void mma16816(float* c, const uint32_t* a,
                                         uint32_t b0, uint32_t b1) {
    asm volatile(
        "mma.sync.aligned.m16n8k16.row.col.f32.f16.f16.f32 "
        "{%0,%1,%2,%3}, {%4,%5,%6,%7}, {%8,%9}, {%0,%1,%2,%3};"
        : "+f"(c[0]), "+f"(c[1]), "+f"(c[2]), "+f"(c[3])
        : "r"(a[0]), "r"(a[1]), "r"(a[2]), "r"(a[3]), "r"(b0), "r"(b1));
}

// SMEM layout (GEMM)
#define OFF_A   0
#define OFF_B0  65536
#define OFF_B1  131072
#define OFF_RB1 196608      // float[256]
#define OFF_RI1 197632      // int[256]
#define OFF_RB2 198656      // float[256]
#define OFF_W2  199680      // float[1024]
#define SMEM_BYTES 203776

// SMEM layout (rescore, dynamic): 4 tokens/block, triple-buffered stages
#define RS_Z    0           // float[4][256]  (4KB)
#define RS_BUF  4096        // 3 x 32KB stage buffers (8 k-rows each)
#define RS_RV   102400      // float[4][256]  (4KB)
#define RS_RIX  106496      // int[4][256]    (4KB)
#define RS_BYTES 110592

// ============================ fused convert z + prep w =======================
// grid 2048 x 256: all blocks grid-stride convert z; blocks 0-127 also prep w
// (fp16 codebook, transposed fp32 codebook, ||w||^2); blocks 0-3 zero counts.
__global__ void prep_all_kernel(const float* __restrict__ z, const float* __restrict__ w) {
    const int tid = threadIdx.x;
    const int bid = blockIdx.x;
    if (bid < 4) {
        g_counts[bid * 256 + tid] = 0;
        if (bid == 0 && tid == 0) g_nflag = 0;
    }
    if (bid < 128) {
        const int code = (bid * 256 + tid) >> 5;   // one warp per code
        const int lane = tid & 31;
        const float4* src = (const float4*)(w + (size_t)code * D);
        float4 v0 = src[lane * 2];
        float4 v1 = src[lane * 2 + 1];
        float s = v0.x * v0.x + v0.y * v0.y + v0.z * v0.z + v0.w * v0.w
                + v1.x * v1.x + v1.y * v1.y + v1.z * v1.z + v1.w * v1.w;
        __half2 h0 = __floats2half2_rn(v0.x, v0.y);
        __half2 h1 = __floats2half2_rn(v0.z, v0.w);
        __half2 h2 = __floats2half2_rn(v1.x, v1.y);
        __half2 h3 = __floats2half2_rn(v1.z, v1.w);
        uint4 u;
        u.x = *(uint32_t*)&h0; u.y = *(uint32_t*)&h1;
        u.z = *(uint32_t*)&h2; u.w = *(uint32_t*)&h3;
        *(uint4*)(g_wh + (size_t)code * D + lane * 8) = u;
        const int k0 = lane * 8;
        g_wT[(size_t)(k0 + 0) * KCODES + code] = v0.x;
        g_wT[(size_t)(k0 + 1) * KCODES + code] = v0.y;
        g_wT[(size_t)(k0 + 2) * KCODES + code] = v0.z;
        g_wT[(size_t)(k0 + 3) * KCODES + code] = v0.w;
        g_wT[(size_t)(k0 + 4) * KCODES + code] = v1.x;
        g_wT[(size_t)(k0 + 5) * KCODES + code] = v1.y;
        g_wT[(size_t)(k0 + 6) * KCODES + code] = v1.z;
        g_wT[(size_t)(k0 + 7) * KCODES + code] = v1.w;
#pragma unroll
        for (int o = 16; o; o >>= 1) s += __shfl_xor_sync(0xffffffffu, s, o);
        if (lane == 0) g_w2[code] = s;
    }
    const int nz4 = N_MAX * D / 4;
    for (int i = bid * 256 + tid; i < nz4; i += gridDim.x * 256) {
        float4 v = ((const float4*)z)[i];
        __half2 h0 = __floats2half2_rn(v.x, v.y);
        __half2 h1 = __floats2half2_rn(v.z, v.w);
        uint2 u;
        u.x = *(uint32_t*)&h0;
        u.y = *(uint32_t*)&h1;
        ((uint2*)g_zh)[i] = u;
    }
}

// ============================ GEMM + fused argmin (512 thr, round-9) =========
__global__ void __launch_bounds__(512, 1)
vq_gemm_kernel(float* __restrict__ out_idx_f) {
    extern __shared__ __align__(128) char smem[];
    const int tid = threadIdx.x;
    const int lane = tid & 31;
    const int wid = tid >> 5;
    const int wm = wid & 7;          // 8 row bands of 16
    const int wn = wid >> 3;         // 2 col bands of 64
    const int row_w = wm * 16;
    const int col_w = wn * 64;
    const int row0 = blockIdx.x * BM;

    const uint32_t sb = smem_u32(smem);
    const uint32_t sA = sb + OFF_A;
    float* redB1 = (float*)(smem + OFF_RB1);
    int*   redI1 = (int*)(smem + OFF_RI1);
    float* redB2 = (float*)(smem + OFF_RB2);
    float* sw2   = (float*)(smem + OFF_W2);

    {
        const __half* zA = g_zh + (size_t)row0 * D;
#pragma unroll
        for (int i = 0; i < 8; i++) {
            int idx = tid + i * 512;
            int r = idx >> 5, c = idx & 31;
            cp16(sA + r * 512 + (((c & 24) | ((c ^ (r & 7)) & 7)) << 4),
                 zA + (size_t)r * D + c * 8);
        }
    }
#pragma unroll
    for (int i = 0; i < 8; i++) {
        int idx = tid + i * 512;
        int r = idx >> 5, c = idx & 31;
        cp16(sb + OFF_B0 + r * 512 + (((c & 24) | ((c ^ (r & 7)) & 7)) << 4),
             g_wh + (size_t)r * D + c * 8);
    }
    CP_COMMIT();

#pragma unroll
    for (int i = 0; i < 2; i++) sw2[tid + i * 512] = g_w2[tid + i * 512];

    float rb1 = FLT_MAX, rb2 = FLT_MAX;
    int ri1 = 0;
    const int within = lane & 7;
    const int sel = lane >> 3;

    for (int nc = 0; nc < NC_IT; nc++) {
        CP_WAIT0();
        __syncthreads();
        if (nc < NC_IT - 1) {
            const __half* src = g_wh + (size_t)(nc + 1) * BN * D;
            uint32_t dstb = sb + ((nc + 1) & 1 ? OFF_B1 : OFF_B0);
#pragma unroll
            for (int i = 0; i < 8; i++) {
                int idx = tid + i * 512;
                int r = idx >> 5, c = idx & 31;
                cp16(dstb + r * 512 + (((c & 24) | ((c ^ (r & 7)) & 7)) << 4),
                     src + (size_t)r * D + c * 8);
            }
            CP_COMMIT();
        }
        const uint32_t sBc = sb + ((nc & 1) ? OFF_B1 : OFF_B0);

        float cacc[8][4];
#pragma unroll
        for (int ni = 0; ni < 8; ni++)
#pragma unroll
            for (int e = 0; e < 4; e++) cacc[ni][e] = 0.f;

#pragma unroll
        for (int ks = 0; ks < 16; ks++) {
            uint32_t a[4];
            {
                int ra = row_w + ((sel & 1) << 3) + within;
                int ca = ks * 2 + (sel >> 1);
                ldsm4(a, sA + ra * 512 + (((ca & 24) | ((ca ^ (ra & 7)) & 7)) << 4));
            }
            uint32_t b[4][4];
#pragma unroll
            for (int p = 0; p < 4; p++) {
                int rb = col_w + p * 16 + ((sel >> 1) << 3) + within;
                int cb = ks * 2 + (sel & 1);
                ldsm4(b[p], sBc + rb * 512 + (((cb & 24) | ((cb ^ (rb & 7)) & 7)) << 4));
            }
#pragma unroll
            for (int ni = 0; ni < 8; ni++) {
                const int p = ni >> 1;
                if (ni & 1) mma16816(cacc[ni], a, b[p][2], b[p][3]);
                else        mma16816(cacc[ni], a, b[p][0], b[p][1]);
            }
        }

#pragma unroll
        for (int h = 0; h < 2; h++) {
            float v1 = FLT_MAX, v2 = FLT_MAX;
            int j1 = 0;
#pragma unroll
            for (int ni = 0; ni < 8; ni++)
#pragma unroll
                for (int e = 0; e < 2; e++) {
                    int gcol = nc * BN + col_w + ni * 8 + ((lane & 3) << 1) + e;
                    float sc = sw2[gcol] - 2.f * cacc[ni][h * 2 + e];
                    if (sc < v1) { v2 = v1; v1 = sc; j1 = gcol; }
                    else if (sc < v2) v2 = sc;
                }
#pragma unroll
            for (int off = 1; off <= 2; off <<= 1) {
                float o1 = __shfl_xor_sync(0xffffffffu, v1, off);
                int oj   = __shfl_xor_sync(0xffffffffu, j1, off);
                float o2 = __shfl_xor_sync(0xffffffffu, v2, off);
                if (o1 < v1 || (o1 == v1 && oj < j1)) {
                    v2 = fminf(v1, o2); v1 = o1; j1 = oj;
                } else {
                    v2 = fminf(v2, o1);
                }
            }
            if ((lane & 3) == 0) {
                int r = row_w + (lane >> 2) + h * 8;
                redB1[wn * 128 + r] = v1;
                redI1[wn * 128 + r] = j1;
                redB2[wn * 128 + r] = v2;
            }
        }
        __syncthreads();
        if (tid < 128) {
            float a1 = redB1[tid], a2 = redB2[tid];
            int aj = redI1[tid];
            float c1 = redB1[128 + tid], c2 = redB2[128 + tid];
            int cj = redI1[128 + tid];
            if (c1 < a1 || (c1 == a1 && cj < aj)) { a2 = fminf(a1, c2); a1 = c1; aj = cj; }
            else a2 = fminf(a2, c1);
            if (a1 < rb1 || (a1 == rb1 && aj < ri1)) { rb2 = fminf(rb1, a2); rb1 = a1; ri1 = aj; }
            else rb2 = fminf(rb2, a1);
        }
        __syncthreads();
    }

    if (tid < 128) {
        int row = row0 + tid;
        g_idx[row] = ri1;
        out_idx_f[row] = (float)ri1;
        atomicAdd(&g_counts[ri1], 1);
        if (rb2 - rb1 < TAU) {
            int p = atomicAdd(&g_nflag, 1);
            g_flag[p] = row;
        }
    }
}

// ============================ Exact rescore (triple-buffered cp.async) =======
// 4 tokens/block; thread owns 4 consecutive codes. wT streamed in 32 stages
// of 8 k-rows (32KB) through a 3-buffer ring. ONE barrier per stage: with
// triple buffering, buffer (s+2)%3 was last read at stage s-1, and the
// prefetch for s+2 is issued AFTER the stage-s barrier (all threads are past
// stage s-1's compute), so no second barrier is needed. wait_group 1 gives
// each stage's fetch a full stage of lookahead.
__global__ void __launch_bounds__(256)
rescore_kernel(const float* __restrict__ z, float* __restrict__ out_idx_f) {
    extern __shared__ __align__(128) char rsm[];
    float (*zs)[D] = (float(*)[D])(rsm + RS_Z);
    float (*rv)[256] = (float(*)[256])(rsm + RS_RV);
    int   (*rix)[256] = (int(*)[256])(rsm + RS_RIX);
    const uint32_t sbuf = smem_u32(rsm) + RS_BUF;
    const int tid = threadIdx.x;
    const int nf = g_nflag;

    for (int base = blockIdx.x * 4; base < nf; base += gridDim.x * 4) {
        CP_WAIT0();
        __syncthreads();
        for (int j = tid; j < 4 * D; j += 256) {
            int t = j >> 8;
            int tok = (base + t < nf) ? g_flag[base + t] : g_flag[base];
            zs[t][j & 255] = z[(size_t)tok * D + (j & 255)];
        }
        __syncthreads();

        // prefill stages 0 and 1 (bufs 0, 1)
#pragma unroll
        for (int p = 0; p < 2; p++) {
            const float* src = g_wT + (size_t)p * 8 * KCODES;
            uint32_t dst = sbuf + p * 32768;
#pragma unroll
            for (int i = 0; i < 8; i++) {
                int idx = tid + i * 256;
                int row = idx >> 8, col = idx & 255;
                cp16(dst + row * 4096 + col * 16, src + (size_t)row * KCODES + col * 4);
            }
            CP_COMMIT();
        }

        float acc[4][4];
#pragma unroll
        for (int t = 0; t < 4; t++)
#pragma unroll
            for (int j = 0; j < 4; j++) acc[t][j] = 0.f;

        int buf = 0;   // buffer holding stage s
        for (int s = 0; s < 32; s++) {
            CP_WAIT1();          // stage s done (s+1 still in flight)
            __syncthreads();     // data visible block-wide; all past stage s-1

            // prefetch stage s+2 into buffer (buf+2)%3 (read last at s-1)
            if (s + 2 < 32) {
                const float* src = g_wT + (size_t)(s + 2) * 8 * KCODES;
                int b2 = buf + 2; if (b2 >= 3) b2 -= 3;
                uint32_t dst = sbuf + b2 * 32768;
#pragma unroll
                for (int i = 0; i < 8; i++) {
                    int idx = tid + i * 256;
                    int row = idx >> 8, col = idx & 255;
                    cp16(dst + row * 4096 + col * 16, src + (size_t)row * KCODES + col * 4);
                }
            }
            CP_COMMIT();         // real or empty: one group per stage

            const char* cur = rsm + RS_BUF + buf * 32768;
#pragma unroll
            for (int u = 0; u < 8; u++) {
                float4 wv = *(const float4*)(cur + u * 4096 + tid * 16);
                const int k = s * 8 + u;
                float z0 = zs[0][k], z1 = zs[1][k], z2 = zs[2][k], z3 = zs[3][k];
                acc[0][0] += wv.x * z0; acc[0][1] += wv.y * z0;
                acc[0][2] += wv.z * z0; acc[0][3] += wv.w * z0;
                acc[1][0] += wv.x * z1; acc[1][1] += wv.y * z1;
                acc[1][2] += wv.z * z1; acc[1][3] += wv.w * z1;
                acc[2][0] += wv.x * z2; acc[2][1] += wv.y * z2;
                acc[2][2] += wv.z * z2; acc[2][3] += wv.w * z2;
                acc[3][0] += wv.x * z3; acc[3][1] += wv.y * z3;
                acc[3][2] += wv.z * z3; acc[3][3] += wv.w * z3;
            }
            if (++buf == 3) buf = 0;
        }

        float4 w2v = ((const float4*)g_w2)[tid];
#pragma unroll
        for (int t = 0; t < 4; t++) {
            float s0 = w2v.x - 2.f * acc[t][0];
            float s1 = w2v.y - 2.f * acc[t][1];
            float s2 = w2v.z - 2.f * acc[t][2];
            float s3 = w2v.w - 2.f * acc[t][3];
            float bv = s0; int bj = 0;
            if (s1 < bv) { bv = s1; bj = 1; }
            if (s2 < bv) { bv = s2; bj = 2; }
            if (s3 < bv) { bv = s3; bj = 3; }
            rv[t][tid] = bv;
            rix[t][tid] = tid * 4 + bj;
        }
        __syncthreads();
        for (int off = 128; off; off >>= 1) {
            if (tid < off) {
#pragma unroll
                for (int t = 0; t < 4; t++) {
                    float ov = rv[t][tid + off]; int oi = rix[t][tid + off];
                    if (ov < rv[t][tid] || (ov == rv[t][tid] && oi < rix[t][tid])) {
                        rv[t][tid] = ov; rix[t][tid] = oi;
                    }
                }
            }
            __syncthreads();
        }
        if (tid < 4 && base + tid < nf) {
            int tok = g_flag[base + tid];
            int ni = rix[tid][0], old = g_idx[tok];
            if (ni != old) {
                atomicSub(&g_counts[old], 1);
                atomicAdd(&g_counts[ni], 1);
                g_idx[tok] = ni;
                out_idx_f[tok] = (float)ni;
            }
        }
    }
}

// ============================ Gather + loss (after rescore) ==================
__global__ void gather_kernel(const float* __restrict__ z, const float* __restrict__ w,
                              float* __restrict__ out_zq) {
    __shared__ float sred[8];
    const int tid = threadIdx.x;
    const int sub = tid >> 6;
    const int t = tid & 63;
    const int token = blockIdx.x * 4 + sub;
    const int idx = g_idx[token];
    float4 q = *(const float4*)&w[(size_t)idx * D + t * 4];
    float4 v = *(const float4*)&z[(size_t)token * D + t * 4];
    float* o = &out_zq[(size_t)token * D + t * 4];
    o[0] = q.x; o[1] = q.y; o[2] = q.z; o[3] = q.w;   // scalar: out_zq 4B-aligned
    float dx = q.x - v.x, dy = q.y - v.y, dz = q.z - v.z, dw = q.w - v.w;
    float s = dx * dx + dy * dy + dz * dz + dw * dw;
#pragma unroll
    for (int o2 = 16; o2; o2 >>= 1) s += __shfl_xor_sync(0xffffffffu, s, o2);
    if ((tid & 31) == 0) sred[tid >> 5] = s;
    __syncthreads();
    if (tid < 4) g_partials[blockIdx.x * 4 + tid] = sred[2 * tid] + sred[2 * tid + 1];
}

// ============================ Finalize =======================================
__global__ void finalize_kernel(float* __restrict__ out_loss,
                                float* __restrict__ out_perp, int N) {
    __shared__ float red[1024];
    int t = threadIdx.x;
    float s = 0.f;
    for (int i = t; i < N; i += 1024) s += g_partials[i];
    red[t] = s;
    __syncthreads();
#pragma unroll
    for (int o = 512; o; o >>= 1) {
        if (t < o) red[t] += red[t + o];
        __syncthreads();
    }
    if (t == 0) out_loss[0] = 0.25f * red[0] / (float)(N * D);
    __syncthreads();
    float e = (float)g_counts[t] / (float)N;
    red[t] = e * logf(e + 1e-10f);
    __syncthreads();
#pragma unroll
    for (int o = 512; o; o >>= 1) {
        if (t < o) red[t] += red[t + o];
        __syncthreads();
    }
    if (t == 0) out_perp[0] = expf(-red[0]);
}

// ============================================================================
extern "C" void kernel_launch(void* const* d_in, const int* in_sizes, int n_in,
                              void* d_out, int out_size) {
    const float* z = (const float*)d_in[0];
    const float* w = (const float*)d_in[1];
    float* out = (float*)d_out;

    const int N = in_sizes[0] / D;  // 32768

    float* out_loss = out;
    float* out_zq   = out + 1;
    float* out_idx  = out + 1 + (size_t)N * D;
    float* out_perp = out + 1 + (size_t)N * D + N;

    cudaFuncSetAttribute(vq_gemm_kernel,
                         cudaFuncAttributeMaxDynamicSharedMemorySize, SMEM_BYTES);
    cudaFuncSetAttribute(rescore_kernel,
                         cudaFuncAttributeMaxDynamicSharedMemorySize, RS_BYTES);

    prep_all_kernel<<<2048, 256>>>(z, w);
    vq_gemm_kernel<<<N / BM, 512, SMEM_BYTES>>>(out_idx);
    rescore_kernel<<<256, 256, RS_BYTES>>>(z, out_idx);
    gather_kernel<<<N / 4, 256>>>(z, w, out_zq);
    finalize_kernel<<<1, 1024>>>(out_loss, out_perp, N);
}

// round 17
// speedup vs baseline: 1.6298x; 1.0320x over previous
#include <cuda_runtime.h>
#include <cuda_fp16.h>
#include <math.h>
#include <stdint.h>
#include <float.h>

#define D 256
#define KCODES 1024
#define N_MAX 32768
#define TAU 0.15f

#define BM 128
#define BN 128
#define NC_IT (KCODES / BN)   // 8

// Scratch (no cudaMalloc allowed)
__device__ __align__(128) float g_w2[KCODES];
__device__ int   g_idx[N_MAX];
__device__ int   g_counts[KCODES];
__device__ float g_partials[N_MAX];   // ||z_tok||^2
__device__ float g_score[N_MAX];      // s* = ||w_idx||^2 - 2 z.w_idx
__device__ int   g_flag[N_MAX];
__device__ int   g_nflag;
__device__ __align__(128) __half g_zh[(size_t)N_MAX * D];      // 16MB
__device__ __align__(128) __half g_wh[(size_t)KCODES * D];     // 512KB
__device__ __align__(128) float  g_wT[(size_t)D * KCODES];     // 1MB transposed

// ============================ PTX helpers (non-'a' arch only) ================
__device__ __forceinline__ uint32_t smem_u32(const void* p) {
    uint32_t a;
    asm("{ .reg .u64 t; cvta.to.shared.u64 t, %1; cvt.u32.u64 %0, t; }"
        : "=r"(a) : "l"(p));
    return a;
}
__device__ __forceinline__ void cp16(uint32_t dst, const void* src) {
    asm volatile("cp.async.cg.shared.global [%0], [%1], 16;" :: "r"(dst), "l"(src));
}
#define CP_COMMIT() asm volatile("cp.async.commit_group;" ::: "memory")
#define CP_WAIT0()  asm volatile("cp.async.wait_group 0;"  ::: "memory")
#define CP_WAIT1()  asm volatile("cp.async.wait_group 1;"  ::: "memory")

__device__ __forceinline__ void ldsm4(uint32_t* r, uint32_t addr) {
    asm volatile("ldmatrix.sync.aligned.m8n8.x4.shared.b16 {%0,%1,%2,%3}, [%4];"
        : "=r"(r[0]), "=r"(r[1]), "=r"(r[2]), "=r"(r[3]) : "r"(addr));
}
__device__ __forceinline__ void mma16816(float* c, const uint32_t* a,
                                         uint32_t b0, uint32_t b1) {
    asm volatile(
        "mma.sync.aligned.m16n8k16.row.col.f32.f16.f16.f32 "
        "{%0,%1,%2,%3}, {%4,%5,%6,%7}, {%8,%9}, {%0,%1,%2,%3};"
        : "+f"(c[0]), "+f"(c[1]), "+f"(c[2]), "+f"(c[3])
        : "r"(a[0]), "r"(a[1]), "r"(a[2]), "r"(a[3]), "r"(b0), "r"(b1));
}

// SMEM layout (GEMM)
#define OFF_A   0
#define OFF_B0  65536
#define OFF_B1  131072
#define OFF_RB1 196608      // float[256]
#define OFF_RI1 197632      // int[256]
#define OFF_RB2 198656      // float[256]
#define OFF_W2  199680      // float[1024]
#define SMEM_BYTES 203776

// SMEM layout (rescore, dynamic): 4 tokens/block, triple-buffered stages
#define RS_Z    0           // float[4][256]  (4KB)
#define RS_BUF  4096        // 3 x 32KB stage buffers (8 k-rows each)
#define RS_RV   102400      // float[4][256]  (4KB)
#define RS_RIX  106496      // int[4][256]    (4KB)
#define RS_BYTES 110592

// ============================ fused prep: counts + w prep + z prep ===========
// grid 2048 x 256. Blocks 0-3 zero counts. Blocks 0-127 prep w (fp16, wT,
// ||w||^2). All blocks grid-stride warp-per-token over z: convert to fp16 AND
// emit ||z_tok||^2 into g_partials (loss identity: ||zq-z||^2 = s* + ||z||^2).
__global__ void prep_all_kernel(const float* __restrict__ z, const float* __restrict__ w) {
    const int tid = threadIdx.x;
    const int bid = blockIdx.x;
    const int lane = tid & 31;
    if (bid < 4) {
        g_counts[bid * 256 + tid] = 0;
        if (bid == 0 && tid == 0) g_nflag = 0;
    }
    if (bid < 128) {
        const int code = (bid * 256 + tid) >> 5;   // one warp per code
        const float4* src = (const float4*)(w + (size_t)code * D);
        float4 v0 = src[lane * 2];
        float4 v1 = src[lane * 2 + 1];
        float s = v0.x * v0.x + v0.y * v0.y + v0.z * v0.z + v0.w * v0.w
                + v1.x * v1.x + v1.y * v1.y + v1.z * v1.z + v1.w * v1.w;
        __half2 h0 = __floats2half2_rn(v0.x, v0.y);
        __half2 h1 = __floats2half2_rn(v0.z, v0.w);
        __half2 h2 = __floats2half2_rn(v1.x, v1.y);
        __half2 h3 = __floats2half2_rn(v1.z, v1.w);
        uint4 u;
        u.x = *(uint32_t*)&h0; u.y = *(uint32_t*)&h1;
        u.z = *(uint32_t*)&h2; u.w = *(uint32_t*)&h3;
        *(uint4*)(g_wh + (size_t)code * D + lane * 8) = u;
        const int k0 = lane * 8;
        g_wT[(size_t)(k0 + 0) * KCODES + code] = v0.x;
        g_wT[(size_t)(k0 + 1) * KCODES + code] = v0.y;
        g_wT[(size_t)(k0 + 2) * KCODES + code] = v0.z;
        g_wT[(size_t)(k0 + 3) * KCODES + code] = v0.w;
        g_wT[(size_t)(k0 + 4) * KCODES + code] = v1.x;
        g_wT[(size_t)(k0 + 5) * KCODES + code] = v1.y;
        g_wT[(size_t)(k0 + 6) * KCODES + code] = v1.z;
        g_wT[(size_t)(k0 + 7) * KCODES + code] = v1.w;
#pragma unroll
        for (int o = 16; o; o >>= 1) s += __shfl_xor_sync(0xffffffffu, s, o);
        if (lane == 0) g_w2[code] = s;
    }
    // warp-per-token z prep: 16384 warps, 32768 tokens -> grid-stride by 2
    const int gwarp = (bid * 256 + tid) >> 5;   // 0..16383
    for (int tok = gwarp; tok < N_MAX; tok += 16384) {
        const float4* src = (const float4*)(z + (size_t)tok * D);
        float4 v0 = src[lane * 2];
        float4 v1 = src[lane * 2 + 1];
        float s = v0.x * v0.x + v0.y * v0.y + v0.z * v0.z + v0.w * v0.w
                + v1.x * v1.x + v1.y * v1.y + v1.z * v1.z + v1.w * v1.w;
        __half2 h0 = __floats2half2_rn(v0.x, v0.y);
        __half2 h1 = __floats2half2_rn(v0.z, v0.w);
        __half2 h2 = __floats2half2_rn(v1.x, v1.y);
        __half2 h3 = __floats2half2_rn(v1.z, v1.w);
        uint4 u;
        u.x = *(uint32_t*)&h0; u.y = *(uint32_t*)&h1;
        u.z = *(uint32_t*)&h2; u.w = *(uint32_t*)&h3;
        *(uint4*)(g_zh + (size_t)tok * D + lane * 8) = u;
#pragma unroll
        for (int o = 16; o; o >>= 1) s += __shfl_xor_sync(0xffffffffu, s, o);
        if (lane == 0) g_partials[tok] = s;
    }
}

// ============================ GEMM + fused argmin (512 thr) ==================
__global__ void __launch_bounds__(512, 1)
vq_gemm_kernel(float* __restrict__ out_idx_f) {
    extern __shared__ __align__(128) char smem[];
    const int tid = threadIdx.x;
    const int lane = tid & 31;
    const int wid = tid >> 5;
    const int wm = wid & 7;          // 8 row bands of 16
    const int wn = wid >> 3;         // 2 col bands of 64
    const int row_w = wm * 16;
    const int col_w = wn * 64;
    const int row0 = blockIdx.x * BM;

    const uint32_t sb = smem_u32(smem);
    const uint32_t sA = sb + OFF_A;
    float* redB1 = (float*)(smem + OFF_RB1);
    int*   redI1 = (int*)(smem + OFF_RI1);
    float* redB2 = (float*)(smem + OFF_RB2);
    float* sw2   = (float*)(smem + OFF_W2);

    {
        const __half* zA = g_zh + (size_t)row0 * D;
#pragma unroll
        for (int i = 0; i < 8; i++) {
            int idx = tid + i * 512;
            int r = idx >> 5, c = idx & 31;
            cp16(sA + r * 512 + (((c & 24) | ((c ^ (r & 7)) & 7)) << 4),
                 zA + (size_t)r * D + c * 8);
        }
    }
#pragma unroll
    for (int i = 0; i < 8; i++) {
        int idx = tid + i * 512;
        int r = idx >> 5, c = idx & 31;
        cp16(sb + OFF_B0 + r * 512 + (((c & 24) | ((c ^ (r & 7)) & 7)) << 4),
             g_wh + (size_t)r * D + c * 8);
    }
    CP_COMMIT();

#pragma unroll
    for (int i = 0; i < 2; i++) sw2[tid + i * 512] = g_w2[tid + i * 512];

    float rb1 = FLT_MAX, rb2 = FLT_MAX;
    int ri1 = 0;
    const int within = lane & 7;
    const int sel = lane >> 3;

    for (int nc = 0; nc < NC_IT; nc++) {
        CP_WAIT0();
        __syncthreads();
        if (nc < NC_IT - 1) {
            const __half* src = g_wh + (size_t)(nc + 1) * BN * D;
            uint32_t dstb = sb + ((nc + 1) & 1 ? OFF_B1 : OFF_B0);
#pragma unroll
            for (int i = 0; i < 8; i++) {
                int idx = tid + i * 512;
                int r = idx >> 5, c = idx & 31;
                cp16(dstb + r * 512 + (((c & 24) | ((c ^ (r & 7)) & 7)) << 4),
                     src + (size_t)r * D + c * 8);
            }
            CP_COMMIT();
        }
        const uint32_t sBc = sb + ((nc & 1) ? OFF_B1 : OFF_B0);

        float cacc[8][4];
#pragma unroll
        for (int ni = 0; ni < 8; ni++)
#pragma unroll
            for (int e = 0; e < 4; e++) cacc[ni][e] = 0.f;

#pragma unroll
        for (int ks = 0; ks < 16; ks++) {
            uint32_t a[4];
            {
                int ra = row_w + ((sel & 1) << 3) + within;
                int ca = ks * 2 + (sel >> 1);
                ldsm4(a, sA + ra * 512 + (((ca & 24) | ((ca ^ (ra & 7)) & 7)) << 4));
            }
            uint32_t b[4][4];
#pragma unroll
            for (int p = 0; p < 4; p++) {
                int rb = col_w + p * 16 + ((sel >> 1) << 3) + within;
                int cb = ks * 2 + (sel & 1);
                ldsm4(b[p], sBc + rb * 512 + (((cb & 24) | ((cb ^ (rb & 7)) & 7)) << 4));
            }
#pragma unroll
            for (int ni = 0; ni < 8; ni++) {
                const int p = ni >> 1;
                if (ni & 1) mma16816(cacc[ni], a, b[p][2], b[p][3]);
                else        mma16816(cacc[ni], a, b[p][0], b[p][1]);
            }
        }

#pragma unroll
        for (int h = 0; h < 2; h++) {
            float v1 = FLT_MAX, v2 = FLT_MAX;
            int j1 = 0;
#pragma unroll
            for (int ni = 0; ni < 8; ni++)
#pragma unroll
                for (int e = 0; e < 2; e++) {
                    int gcol = nc * BN + col_w + ni * 8 + ((lane & 3) << 1) + e;
                    float sc = sw2[gcol] - 2.f * cacc[ni][h * 2 + e];
                    if (sc < v1) { v2 = v1; v1 = sc; j1 = gcol; }
                    else if (sc < v2) v2 = sc;
                }
#pragma unroll
            for (int off = 1; off <= 2; off <<= 1) {
                float o1 = __shfl_xor_sync(0xffffffffu, v1, off);
                int oj   = __shfl_xor_sync(0xffffffffu, j1, off);
                float o2 = __shfl_xor_sync(0xffffffffu, v2, off);
                if (o1 < v1 || (o1 == v1 && oj < j1)) {
                    v2 = fminf(v1, o2); v1 = o1; j1 = oj;
                } else {
                    v2 = fminf(v2, o1);
                }
            }
            if ((lane & 3) == 0) {
                int r = row_w + (lane >> 2) + h * 8;
                redB1[wn * 128 + r] = v1;
                redI1[wn * 128 + r] = j1;
                redB2[wn * 128 + r] = v2;
            }
        }
        __syncthreads();
        if (tid < 128) {
            float a1 = redB1[tid], a2 = redB2[tid];
            int aj = redI1[tid];
            float c1 = redB1[128 + tid], c2 = redB2[128 + tid];
            int cj = redI1[128 + tid];
            if (c1 < a1 || (c1 == a1 && cj < aj)) { a2 = fminf(a1, c2); a1 = c1; aj = cj; }
            else a2 = fminf(a2, c1);
            if (a1 < rb1 || (a1 == rb1 && aj < ri1)) { rb2 = fminf(rb1, a2); rb1 = a1; ri1 = aj; }
            else rb2 = fminf(rb2, a1);
        }
        __syncthreads();
    }

    if (tid < 128) {
        int row = row0 + tid;
        g_idx[row] = ri1;
        g_score[row] = rb1;            // s* for the loss identity
        out_idx_f[row] = (float)ri1;
        atomicAdd(&g_counts[ri1], 1);
        if (rb2 - rb1 < TAU) {
            int p = atomicAdd(&g_nflag, 1);
            g_flag[p] = row;
        }
    }
}

// ============================ Exact rescore (triple-buffered cp.async) =======
__global__ void __launch_bounds__(256)
rescore_kernel(const float* __restrict__ z, float* __restrict__ out_idx_f) {
    extern __shared__ __align__(128) char rsm[];
    float (*zs)[D] = (float(*)[D])(rsm + RS_Z);
    float (*rv)[256] = (float(*)[256])(rsm + RS_RV);
    int   (*rix)[256] = (int(*)[256])(rsm + RS_RIX);
    const uint32_t sbuf = smem_u32(rsm) + RS_BUF;
    const int tid = threadIdx.x;
    const int nf = g_nflag;

    for (int base = blockIdx.x * 4; base < nf; base += gridDim.x * 4) {
        CP_WAIT0();
        __syncthreads();
        for (int j = tid; j < 4 * D; j += 256) {
            int t = j >> 8;
            int tok = (base + t < nf) ? g_flag[base + t] : g_flag[base];
            zs[t][j & 255] = z[(size_t)tok * D + (j & 255)];
        }
        __syncthreads();

        // prefill stages 0 and 1
#pragma unroll
        for (int p = 0; p < 2; p++) {
            const float* src = g_wT + (size_t)p * 8 * KCODES;
            uint32_t dst = sbuf + p * 32768;
#pragma unroll
            for (int i = 0; i < 8; i++) {
                int idx = tid + i * 256;
                int row = idx >> 8, col = idx & 255;
                cp16(dst + row * 4096 + col * 16, src + (size_t)row * KCODES + col * 4);
            }
            CP_COMMIT();
        }

        float acc[4][4];
#pragma unroll
        for (int t = 0; t < 4; t++)
#pragma unroll
            for (int j = 0; j < 4; j++) acc[t][j] = 0.f;

        int buf = 0;
        for (int s = 0; s < 32; s++) {
            CP_WAIT1();
            __syncthreads();
            if (s + 2 < 32) {
                const float* src = g_wT + (size_t)(s + 2) * 8 * KCODES;
                int b2 = buf + 2; if (b2 >= 3) b2 -= 3;
                uint32_t dst = sbuf + b2 * 32768;
#pragma unroll
                for (int i = 0; i < 8; i++) {
                    int idx = tid + i * 256;
                    int row = idx >> 8, col = idx & 255;
                    cp16(dst + row * 4096 + col * 16, src + (size_t)row * KCODES + col * 4);
                }
            }
            CP_COMMIT();

            const char* cur = rsm + RS_BUF + buf * 32768;
#pragma unroll
            for (int u = 0; u < 8; u++) {
                float4 wv = *(const float4*)(cur + u * 4096 + tid * 16);
                const int k = s * 8 + u;
                float z0 = zs[0][k], z1 = zs[1][k], z2 = zs[2][k], z3 = zs[3][k];
                acc[0][0] += wv.x * z0; acc[0][1] += wv.y * z0;
                acc[0][2] += wv.z * z0; acc[0][3] += wv.w * z0;
                acc[1][0] += wv.x * z1; acc[1][1] += wv.y * z1;
                acc[1][2] += wv.z * z1; acc[1][3] += wv.w * z1;
                acc[2][0] += wv.x * z2; acc[2][1] += wv.y * z2;
                acc[2][2] += wv.z * z2; acc[2][3] += wv.w * z2;
                acc[3][0] += wv.x * z3; acc[3][1] += wv.y * z3;
                acc[3][2] += wv.z * z3; acc[3][3] += wv.w * z3;
            }
            if (++buf == 3) buf = 0;
        }

        float4 w2v = ((const float4*)g_w2)[tid];
#pragma unroll
        for (int t = 0; t < 4; t++) {
            float s0 = w2v.x - 2.f * acc[t][0];
            float s1 = w2v.y - 2.f * acc[t][1];
            float s2 = w2v.z - 2.f * acc[t][2];
            float s3 = w2v.w - 2.f * acc[t][3];
            float bv = s0; int bj = 0;
            if (s1 < bv) { bv = s1; bj = 1; }
            if (s2 < bv) { bv = s2; bj = 2; }
            if (s3 < bv) { bv = s3; bj = 3; }
            rv[t][tid] = bv;
            rix[t][tid] = tid * 4 + bj;
        }
        __syncthreads();
        for (int off = 128; off; off >>= 1) {
            if (tid < off) {
#pragma unroll
                for (int t = 0; t < 4; t++) {
                    float ov = rv[t][tid + off]; int oi = rix[t][tid + off];
                    if (ov < rv[t][tid] || (ov == rv[t][tid] && oi < rix[t][tid])) {
                        rv[t][tid] = ov; rix[t][tid] = oi;
                    }
                }
            }
            __syncthreads();
        }
        if (tid < 4 && base + tid < nf) {
            int tok = g_flag[base + tid];
            int ni = rix[tid][0], old = g_idx[tok];
            g_score[tok] = rv[tid][0];   // exact s* for flagged tokens
            if (ni != old) {
                atomicSub(&g_counts[old], 1);
                atomicAdd(&g_counts[ni], 1);
                g_idx[tok] = ni;
                out_idx_f[tok] = (float)ni;
            }
        }
    }
}

// ============================ Gather: pure w[idx] -> z_q copy ================
__global__ void gather_kernel(const float* __restrict__ w, float* __restrict__ out_zq) {
    const int tid = threadIdx.x;
    const int sub = tid >> 6;
    const int t = tid & 63;
    const int token = blockIdx.x * 4 + sub;
    const int idx = g_idx[token];
    float4 q = *(const float4*)&w[(size_t)idx * D + t * 4];
    float* o = &out_zq[(size_t)token * D + t * 4];
    o[0] = q.x; o[1] = q.y; o[2] = q.z; o[3] = q.w;   // scalar: out_zq 4B-aligned
}

// ============================ Finalize =======================================
// loss = 0.25 * sum(||z||^2 + s*) / (N*D)
__global__ void finalize_kernel(float* __restrict__ out_loss,
                                float* __restrict__ out_perp, int N) {
    __shared__ float red[1024];
    int t = threadIdx.x;
    float s = 0.f;
    for (int i = t; i < N; i += 1024) s += g_partials[i] + g_score[i];
    red[t] = s;
    __syncthreads();
#pragma unroll
    for (int o = 512; o; o >>= 1) {
        if (t < o) red[t] += red[t + o];
        __syncthreads();
    }
    if (t == 0) out_loss[0] = 0.25f * red[0] / (float)(N * D);
    __syncthreads();
    float e = (float)g_counts[t] / (float)N;
    red[t] = e * logf(e + 1e-10f);
    __syncthreads();
#pragma unroll
    for (int o = 512; o; o >>= 1) {
        if (t < o) red[t] += red[t + o];
        __syncthreads();
    }
    if (t == 0) out_perp[0] = expf(-red[0]);
}

// ============================================================================
extern "C" void kernel_launch(void* const* d_in, const int* in_sizes, int n_in,
                              void* d_out, int out_size) {
    const float* z = (const float*)d_in[0];
    const float* w = (const float*)d_in[1];
    float* out = (float*)d_out;

    const int N = in_sizes[0] / D;  // 32768

    float* out_loss = out;
    float* out_zq   = out + 1;
    float* out_idx  = out + 1 + (size_t)N * D;
    float* out_perp = out + 1 + (size_t)N * D + N;

    cudaFuncSetAttribute(vq_gemm_kernel,
                         cudaFuncAttributeMaxDynamicSharedMemorySize, SMEM_BYTES);
    cudaFuncSetAttribute(rescore_kernel,
                         cudaFuncAttributeMaxDynamicSharedMemorySize, RS_BYTES);

    prep_all_kernel<<<2048, 256>>>(z, w);
    vq_gemm_kernel<<<N / BM, 512, SMEM_BYTES>>>(out_idx);
    rescore_kernel<<<256, 256, RS_BYTES>>>(z, out_idx);
    gather_kernel<<<N / 4, 256>>>(w, out_zq);
    finalize_kernel<<<1, 1024>>>(out_loss, out_perp, N);
}